// round 1
// baseline (speedup 1.0000x reference)
#include <cuda_runtime.h>
#include <cstdint>

#define N 4096
#define D 128

// ---------------- device globals (scratch; no allocations allowed) ----------------
__device__ __align__(16) float g_en[N * D];       // normalized embeddings
__device__ unsigned g_hist1[4096];
__device__ unsigned g_hist2[4096];
__device__ unsigned g_hist3[256];
__device__ unsigned g_zeroPairs;
__device__ unsigned g_prefix1;     // selected top-12 bits
__device__ unsigned g_prefix2;     // selected top-24 bits
__device__ unsigned g_vloBits;     // bit pattern of s_pair[mLo]
__device__ unsigned g_rankRem;     // remaining rank within current bin
__device__ unsigned g_mLo, g_mHi;  // pair ranks for interpolation
__device__ float    g_frac;        // interpolation fraction (replicates jax fp32 math)
__device__ unsigned g_cntLE;
__device__ unsigned g_minAbove;
__device__ float    g_actThresh;
__device__ float    g_noiseThresh;
__device__ unsigned char g_low[N];
__device__ unsigned g_rowMinPos[N];  // encoded min-dot over positive mask
__device__ unsigned g_rowMaxNeg[N];  // encoded max-dot over negative mask

// order-preserving float <-> uint encode
__device__ __forceinline__ unsigned encodeF(float f) {
    unsigned u = __float_as_uint(f);
    return (u & 0x80000000u) ? ~u : (u | 0x80000000u);
}
__device__ __forceinline__ float decodeF(unsigned u) {
    return (u & 0x80000000u) ? __uint_as_float(u & 0x7FFFFFFFu)
                             : __uint_as_float(~u);
}

// ---------------- K0: reset all accumulators (must run every replay) ----------------
__global__ void initK() {
    int i = blockIdx.x * blockDim.x + threadIdx.x;
    int stride = gridDim.x * blockDim.x;
    for (int x = i; x < 4096; x += stride) {
        g_hist1[x] = 0u;
        g_hist2[x] = 0u;
        g_rowMinPos[x] = 0xFFFFFFFFu;
        g_rowMaxNeg[x] = 0u;
    }
    for (int x = i; x < 256; x += stride) g_hist3[x] = 0u;
    if (i == 0) {
        g_zeroPairs = 0u;
        g_cntLE = 0u;
        g_minAbove = 0xFFFFFFFFu;
        g_rankRem = 0u;
    }
}

// ---------------- K1: row-normalize embeddings (one warp per row) ----------------
__global__ void normalizeK(const float* __restrict__ emb) {
    int warp = (blockIdx.x * blockDim.x + threadIdx.x) >> 5;
    int lane = threadIdx.x & 31;
    if (warp >= N) return;
    const float4* p = (const float4*)(emb + (size_t)warp * D);
    float4 v = p[lane];
    float ss = v.x * v.x + v.y * v.y + v.z * v.z + v.w * v.w;
#pragma unroll
    for (int s = 16; s > 0; s >>= 1) ss += __shfl_xor_sync(0xffffffffu, ss, s);
    float inv = 1.0f / fmaxf(sqrtf(ss), 1e-12f);
    float4 o;
    o.x = v.x * inv; o.y = v.y * inv; o.z = v.z * inv; o.w = v.w * inv;
    ((float4*)(g_en + (size_t)warp * D))[lane] = o;
}

// ---------------- K2: bitonic sort of aleatoric uncertainty -> median & low mask ----------------
__global__ void sortAuK(const float* __restrict__ au) {
    __shared__ float s[N];
    __shared__ float thSh;
    int tid = threadIdx.x;  // 1024
    for (int i = tid; i < N; i += 1024) s[i] = au[i];
    __syncthreads();
    for (int k = 2; k <= N; k <<= 1) {
        for (int j = k >> 1; j > 0; j >>= 1) {
            for (int idx = tid; idx < N; idx += 1024) {
                int p = idx ^ j;
                if (p > idx) {
                    float a = s[idx], b = s[p];
                    bool up = ((idx & k) == 0);
                    bool sw = up ? (a > b) : (a < b);
                    if (sw) { s[idx] = b; s[p] = a; }
                }
            }
            __syncthreads();
        }
    }
    if (tid == 0) {
        // pos = 0.5*(4096-1) = 2047.5 exactly -> lerp of s[2047], s[2048]
        float th = 0.5f * s[2047] + 0.5f * s[2048];
        g_noiseThresh = th;
        thSh = th;
    }
    __syncthreads();
    float th = thSh;
    for (int i = tid; i < N; i += 1024) g_low[i] = (au[i] < th) ? 1 : 0;
}

// ---------------- radix-select passes over unordered pairs (j > i) ----------------
template <int PASS>
__global__ void histPass(const float* __restrict__ t) {
    __shared__ float ts[N];
    __shared__ unsigned hist[4096];
    __shared__ unsigned sCnt;
    __shared__ unsigned sMin;
    int tid = threadIdx.x;  // 256
    for (int i = tid; i < N; i += 256) ts[i] = t[i];
    for (int i = tid; i < 4096; i += 256) hist[i] = 0u;
    if (tid == 0) { sCnt = 0u; sMin = 0xFFFFFFFFu; }
    unsigned p1 = g_prefix1, p2 = g_prefix2, vlo = g_vloBits;
    __syncthreads();

    unsigned zc = 0u, cnt = 0u, myMin = 0xFFFFFFFFu;
    for (int i = blockIdx.x; i < N; i += gridDim.x) {
        float ti = ts[i];
        for (int j = i + 1 + tid; j < N; j += 256) {
            float d = fabsf(ti - ts[j]);
            unsigned b = __float_as_uint(d);
            if (b == 0u) { zc++; continue; }  // ties excluded by flat>0 mask
            if (PASS == 1) {
                atomicAdd(&hist[b >> 20], 1u);
            } else if (PASS == 2) {
                if ((b >> 20) == p1) atomicAdd(&hist[(b >> 8) & 0xFFFu], 1u);
            } else if (PASS == 3) {
                if ((b >> 8) == p2) atomicAdd(&hist[b & 0xFFu], 1u);
            } else {
                if (b <= vlo) cnt++;
                else myMin = min(myMin, b);
            }
        }
    }
    __syncthreads();
    if (PASS == 1) {
        for (int i = tid; i < 4096; i += 256)
            if (hist[i]) atomicAdd(&g_hist1[i], hist[i]);
        if (zc) atomicAdd(&sCnt, zc);
        __syncthreads();
        if (tid == 0 && sCnt) atomicAdd(&g_zeroPairs, sCnt);
    } else if (PASS == 2) {
        for (int i = tid; i < 4096; i += 256)
            if (hist[i]) atomicAdd(&g_hist2[i], hist[i]);
    } else if (PASS == 3) {
        for (int i = tid; i < 256; i += 256)
            if (hist[i]) atomicAdd(&g_hist3[i], hist[i]);
    } else {
        if (cnt) atomicAdd(&sCnt, cnt);
        atomicMin(&sMin, myMin);
        __syncthreads();
        if (tid == 0) {
            if (sCnt) atomicAdd(&g_cntLE, sCnt);
            atomicMin(&g_minAbove, sMin);
        }
    }
}

// scan 4096-bin histogram, locate the bin holding the target rank
__global__ void scanSelect(int stage) {
    __shared__ unsigned warpS[32];
    __shared__ unsigned rankSh;
    int tid = threadIdx.x;  // 1024
    int lane = tid & 31, wid = tid >> 5;
    if (tid == 0) {
        unsigned rank;
        if (stage == 1) {
            // replicate jax fp32 rank arithmetic exactly
            unsigned long long n = 16773120ull - 2ull * (unsigned long long)g_zeroPairs;
            float nf = (float)(n - 1ull);          // (n-1).astype(float32)
            float pos = 0.2f * nf;                 // q * (n-1)  [fp32!]
            float lof = floorf(pos);
            g_frac = pos - lof;
            unsigned lo = (unsigned)lof;
            g_mLo = lo >> 1;                       // flat rank -> pair rank
            g_mHi = (lo + 1u) >> 1;
            rank = g_mLo;
        } else {
            rank = g_rankRem;
        }
        rankSh = rank;
    }
    __syncthreads();
    unsigned rank = rankSh;
    unsigned h0, h1, h2, h3;
    if (stage == 1) {
        h0 = g_hist1[tid * 4 + 0]; h1 = g_hist1[tid * 4 + 1];
        h2 = g_hist1[tid * 4 + 2]; h3 = g_hist1[tid * 4 + 3];
    } else {
        h0 = g_hist2[tid * 4 + 0]; h1 = g_hist2[tid * 4 + 1];
        h2 = g_hist2[tid * 4 + 2]; h3 = g_hist2[tid * 4 + 3];
    }
    unsigned lsum = h0 + h1 + h2 + h3;
    unsigned v = lsum;
#pragma unroll
    for (int s = 1; s < 32; s <<= 1) {
        unsigned o = __shfl_up_sync(0xffffffffu, v, s);
        if (lane >= s) v += o;
    }
    if (lane == 31) warpS[wid] = v;
    __syncthreads();
    if (wid == 0) {
        unsigned w = warpS[lane];
#pragma unroll
        for (int s = 1; s < 32; s <<= 1) {
            unsigned o = __shfl_up_sync(0xffffffffu, w, s);
            if (lane >= s) w += o;
        }
        warpS[lane] = w;  // inclusive scan of warp sums
    }
    __syncthreads();
    unsigned base = (v - lsum) + (wid ? warpS[wid - 1] : 0u);
    unsigned cum = base;
    unsigned hs[4] = {h0, h1, h2, h3};
#pragma unroll
    for (int c = 0; c < 4; c++) {
        unsigned h = hs[c];
        if (h && rank >= cum && rank < cum + h) {
            unsigned bin = (unsigned)(tid * 4 + c);
            if (stage == 1) g_prefix1 = bin;
            else g_prefix2 = (g_prefix1 << 12) | bin;
            g_rankRem = rank - cum;
        }
        cum += h;
    }
}

__global__ void scan256K() {
    if (threadIdx.x == 0) {
        unsigned rank = g_rankRem, cum = 0u;
        unsigned p2 = g_prefix2;
        for (int b = 0; b < 256; b++) {
            unsigned h = g_hist3[b];
            if (h && rank >= cum && rank < cum + h) g_vloBits = (p2 << 8) | (unsigned)b;
            cum += h;
        }
    }
}

__global__ void finThreshK() {
    if (threadIdx.x == 0) {
        float vlo = __uint_as_float(g_vloBits);
        float vhi = (g_cntLE >= g_mHi + 1u) ? vlo : __uint_as_float(g_minAbove);
        float f = g_frac;
        g_actThresh = __fadd_rn(__fmul_rn(vlo, 1.0f - f), __fmul_rn(vhi, f));
    }
}

// ---------------- main fused GEMM + masked row reductions ----------------
__global__ __launch_bounds__(256) void gemmMaskK(const float* __restrict__ t) {
    __shared__ __align__(16) float As[32][136];
    __shared__ __align__(16) float Bs[32][136];
    int tid = threadIdx.x;
    int bi = blockIdx.y, bj = blockIdx.x;
    int r0 = (tid >> 4) * 4;     // row fragment base (4+4 split)
    int c0 = (tid & 15) * 4;     // col fragment base (4+4 split)

    float acc[8][8];
#pragma unroll
    for (int r = 0; r < 8; r++)
#pragma unroll
        for (int c = 0; c < 8; c++) acc[r][c] = 0.0f;

    int lr = tid >> 1, lh = tid & 1;
    for (int kc = 0; kc < 4; kc++) {
        const float4* pa = (const float4*)(g_en + (size_t)(bi * 128 + lr) * D + kc * 32 + lh * 16);
        const float4* pb = (const float4*)(g_en + (size_t)(bj * 128 + lr) * D + kc * 32 + lh * 16);
        float4 a0 = pa[0], a1 = pa[1], a2 = pa[2], a3 = pa[3];
        float4 b0 = pb[0], b1 = pb[1], b2 = pb[2], b3 = pb[3];
        if (kc) __syncthreads();  // prior compute must finish before overwrite
        int kb = lh * 16;
        As[kb + 0][lr] = a0.x; As[kb + 1][lr] = a0.y; As[kb + 2][lr] = a0.z; As[kb + 3][lr] = a0.w;
        As[kb + 4][lr] = a1.x; As[kb + 5][lr] = a1.y; As[kb + 6][lr] = a1.z; As[kb + 7][lr] = a1.w;
        As[kb + 8][lr] = a2.x; As[kb + 9][lr] = a2.y; As[kb + 10][lr] = a2.z; As[kb + 11][lr] = a2.w;
        As[kb + 12][lr] = a3.x; As[kb + 13][lr] = a3.y; As[kb + 14][lr] = a3.z; As[kb + 15][lr] = a3.w;
        Bs[kb + 0][lr] = b0.x; Bs[kb + 1][lr] = b0.y; Bs[kb + 2][lr] = b0.z; Bs[kb + 3][lr] = b0.w;
        Bs[kb + 4][lr] = b1.x; Bs[kb + 5][lr] = b1.y; Bs[kb + 6][lr] = b1.z; Bs[kb + 7][lr] = b1.w;
        Bs[kb + 8][lr] = b2.x; Bs[kb + 9][lr] = b2.y; Bs[kb + 10][lr] = b2.z; Bs[kb + 11][lr] = b2.w;
        Bs[kb + 12][lr] = b3.x; Bs[kb + 13][lr] = b3.y; Bs[kb + 14][lr] = b3.z; Bs[kb + 15][lr] = b3.w;
        __syncthreads();
#pragma unroll 8
        for (int k = 0; k < 32; k++) {
            float4 x0 = *(const float4*)&As[k][r0];
            float4 x1 = *(const float4*)&As[k][64 + r0];
            float4 y0 = *(const float4*)&Bs[k][c0];
            float4 y1 = *(const float4*)&Bs[k][64 + c0];
            float a[8] = {x0.x, x0.y, x0.z, x0.w, x1.x, x1.y, x1.z, x1.w};
            float b[8] = {y0.x, y0.y, y0.z, y0.w, y1.x, y1.y, y1.z, y1.w};
#pragma unroll
            for (int r = 0; r < 8; r++)
#pragma unroll
                for (int c = 0; c < 8; c++) acc[r][c] += a[r] * b[c];
        }
    }

    // ---- fused epilogue: masked row min-dot / max-dot ----
    int rows[8], cols[8];
#pragma unroll
    for (int u = 0; u < 4; u++) {
        rows[u] = bi * 128 + r0 + u;
        rows[4 + u] = bi * 128 + 64 + r0 + u;
        cols[u] = bj * 128 + c0 + u;
        cols[4 + u] = bj * 128 + 64 + c0 + u;
    }
    float ti[8], tj[8];
    int lj[8];
#pragma unroll
    for (int u = 0; u < 8; u++) {
        ti[u] = t[rows[u]];
        tj[u] = t[cols[u]];
        lj[u] = g_low[cols[u]];
    }
    float actT = g_actThresh;
    float pMin[8], nMax[8];
#pragma unroll
    for (int r = 0; r < 8; r++) { pMin[r] = 3.402823466e38f; nMax[r] = -3.402823466e38f; }
#pragma unroll
    for (int r = 0; r < 8; r++) {
#pragma unroll
        for (int c = 0; c < 8; c++) {
            float ad = fabsf(ti[r] - tj[c]);
            if (ad < actT) {
                float d = acc[r][c];
                if (lj[c]) {
                    if (rows[r] != cols[c]) pMin[r] = fminf(pMin[r], d);
                } else {
                    nMax[r] = fmaxf(nMax[r], d);
                }
            }
        }
    }
    // reduce across the 16 lanes that share the same row set
#pragma unroll
    for (int s = 8; s > 0; s >>= 1) {
#pragma unroll
        for (int r = 0; r < 8; r++) {
            pMin[r] = fminf(pMin[r], __shfl_down_sync(0xffffffffu, pMin[r], s, 16));
            nMax[r] = fmaxf(nMax[r], __shfl_down_sync(0xffffffffu, nMax[r], s, 16));
        }
    }
    if ((tid & 15) == 0) {
#pragma unroll
        for (int r = 0; r < 8; r++) {
            if (pMin[r] < 3.0e38f) atomicMin(&g_rowMinPos[rows[r]], encodeF(pMin[r]));
            if (nMax[r] > -3.0e38f) atomicMax(&g_rowMaxNeg[rows[r]], encodeF(nMax[r]));
        }
    }
}

// ---------------- final: per-anchor loss + mean ----------------
__global__ void finalK(float* __restrict__ out, int out_size) {
    __shared__ float sSum[32];
    __shared__ unsigned sCnt[32];
    int tid = threadIdx.x;  // 1024
    int lane = tid & 31, wid = tid >> 5;
    float sum = 0.0f;
    unsigned cnt = 0u;
    for (int i = tid; i < N; i += 1024) {
        if (!g_low[i]) continue;
        unsigned ep = g_rowMinPos[i];
        if (ep == 0xFFFFFFFFu) continue;  // no positive
        unsigned en = g_rowMaxNeg[i];
        if (en == 0u) continue;           // no negative
        float minDot = decodeF(ep);
        float maxDot = decodeF(en);
        float hp = sqrtf(fmaxf(2.0f - 2.0f * minDot, 1e-12f));
        float hn = sqrtf(fmaxf(2.0f - 2.0f * maxDot, 1e-12f));
        float tl = hp - hn + 0.5f;
        if (tl < 0.0f) tl = 0.0f;
        sum += tl;
        cnt++;
    }
#pragma unroll
    for (int s = 16; s > 0; s >>= 1) {
        sum += __shfl_down_sync(0xffffffffu, sum, s);
        cnt += __shfl_down_sync(0xffffffffu, cnt, s);
    }
    if (lane == 0) { sSum[wid] = sum; sCnt[wid] = cnt; }
    __syncthreads();
    if (wid == 0) {
        float s2 = sSum[lane];
        unsigned c2 = sCnt[lane];
#pragma unroll
        for (int s = 16; s > 0; s >>= 1) {
            s2 += __shfl_down_sync(0xffffffffu, s2, s);
            c2 += __shfl_down_sync(0xffffffffu, c2, s);
        }
        if (lane == 0) out[0] = s2 / (float)(c2 > 0u ? c2 : 1u);
    }
    for (int i = tid; i < out_size; i += 1024)
        if (i > 0) out[i] = 0.0f;
}

// ---------------- launch ----------------
extern "C" void kernel_launch(void* const* d_in, const int* in_sizes, int n_in,
                              void* d_out, int out_size) {
    const float* emb = (const float*)d_in[0];
    const float* tg = (const float*)d_in[1];
    const float* au = (const float*)d_in[2];
    float* out = (float*)d_out;

    initK<<<32, 256>>>();
    normalizeK<<<128, 1024>>>(emb);
    sortAuK<<<1, 1024>>>(au);
    histPass<1><<<512, 256>>>(tg);
    scanSelect<<<1, 1024>>>(1);
    histPass<2><<<512, 256>>>(tg);
    scanSelect<<<1, 1024>>>(2);
    histPass<3><<<512, 256>>>(tg);
    scan256K<<<1, 32>>>();
    histPass<4><<<512, 256>>>(tg);
    finThreshK<<<1, 32>>>();
    gemmMaskK<<<dim3(32, 32), 256>>>(tg);
    finalK<<<1, 1024>>>(out, out_size);
}